// round 2
// baseline (speedup 1.0000x reference)
#include <cuda_runtime.h>
#include <math.h>

#define NE 32
#define TOPK 4
#define HD 2048
#define ID 1024
#define NT 4096
#define MAXP (NT*TOPK)

// ---- scratch (static device globals; no runtime allocation) ----
__device__ int   d_counts[NE];
__device__ int   d_offsets[NE+1];
__device__ int   d_perm_tok[NE*NT];
__device__ float d_perm_w[NE*NT];
__device__ float d_gu[(size_t)MAXP*2*ID];   // 128 MB
__device__ float d_h[(size_t)MAXP*ID];      // 64 MB

// ---- packed f32x2 helpers (FFMA2 path, rt_SMSP=1 vs 2 for 3-reg FFMA) ----
__device__ __forceinline__ unsigned long long pk2(float lo, float hi) {
    unsigned long long r;
    asm("mov.b64 %0, {%1,%2};" : "=l"(r) : "f"(lo), "f"(hi));
    return r;
}
__device__ __forceinline__ void fma2(unsigned long long& acc, unsigned long long a, unsigned long long b) {
    asm("fma.rn.f32x2 %0, %1, %2, %0;" : "+l"(acc) : "l"(a), "l"(b));
}
__device__ __forceinline__ float2 unpk2(unsigned long long v) {
    float2 r;
    asm("mov.b64 {%0,%1}, %2;" : "=f"(r.x), "=f"(r.y) : "l"(v));
    return r;
}

// ============================================================
// 0) zero output + counts
// ============================================================
__global__ void zero_kernel(float* __restrict__ out) {
    int idx = blockIdx.x * blockDim.x + threadIdx.x;
    int stride = gridDim.x * blockDim.x;
    const int n4 = (NT * HD) / 4;
    float4 z = make_float4(0.f, 0.f, 0.f, 0.f);
    float4* o4 = (float4*)out;
    for (int i = idx; i < n4; i += stride) o4[i] = z;
    if (idx < NE) d_counts[idx] = 0;
}

// ============================================================
// 1) router: logits, sigmoid, biased top-4, renormalized weights,
//    scatter (token, weight) into per-expert lists
// ============================================================
__global__ void router_kernel(const float* __restrict__ x,
                              const float* __restrict__ gw,
                              const float* __restrict__ bias) {
    int t = blockIdx.x;
    int tid = threadIdx.x;        // 256 threads
    int e = tid >> 3;             // 8 threads per expert
    int l8 = tid & 7;
    const float* xr = x + (size_t)t * HD;
    const float* gr = gw + (size_t)e * HD;
    float s = 0.f;
    for (int j = l8; j < HD; j += 8) s = fmaf(xr[j], gr[j], s);
    s += __shfl_down_sync(0xffffffffu, s, 4, 8);
    s += __shfl_down_sync(0xffffffffu, s, 2, 8);
    s += __shfl_down_sync(0xffffffffu, s, 1, 8);
    __shared__ float logits[NE];
    if (l8 == 0) logits[e] = s;
    __syncthreads();
    if (tid == 0) {
        float sc[NE], bs[NE];
        #pragma unroll
        for (int i = 0; i < NE; i++) {
            float v = 1.f / (1.f + expf(-logits[i]));
            sc[i] = v;
            bs[i] = v + bias[i];
        }
        int   idx[TOPK];
        float w[TOPK];
        float sum = 0.f;
        #pragma unroll
        for (int k = 0; k < TOPK; k++) {
            int bi = 0; float bv = -1e30f;
            #pragma unroll
            for (int i = 0; i < NE; i++)
                if (bs[i] > bv) { bv = bs[i]; bi = i; }   // strict > == lowest-index tiebreak
            bs[bi] = -1e30f;
            idx[k] = bi; w[k] = sc[bi]; sum += sc[bi];
        }
        float inv = 1.f / sum;
        #pragma unroll
        for (int k = 0; k < TOPK; k++) {
            int ex = idx[k];
            int pos = atomicAdd(&d_counts[ex], 1);
            d_perm_tok[ex * NT + pos] = t;
            d_perm_w[ex * NT + pos]   = w[k] * inv;
        }
    }
}

// ============================================================
// 2) exclusive scan over 32 counts
// ============================================================
__global__ void offsets_kernel() {
    int acc = 0;
    for (int i = 0; i < NE; i++) { d_offsets[i] = acc; acc += d_counts[i]; }
    d_offsets[NE] = acc;
}

// ============================================================
// Grouped SGEMM: 128x128x8 tile, 256 threads, TM=TN=8, f32x2 FMAs
// ============================================================
#define BM 128
#define BN 128
#define BK 8

// GEMM1: gu[base+m][n] = sum_k x[tok[m]][k] * w13_e[n][k]   (N=2*ID, K=HD)
__global__ __launch_bounds__(256) void gemm1_kernel(const float* __restrict__ x,
                                                    const float* __restrict__ w13) {
    int e = blockIdx.z;
    int cnt = d_counts[e];
    int m0 = blockIdx.y * BM;
    if (m0 >= cnt) return;
    int n0 = blockIdx.x * BN;
    int base = d_offsets[e];
    const float* W = w13 + (size_t)e * (2 * ID) * HD;

    __shared__ __align__(16) float As[BK][BM + 4];
    __shared__ __align__(16) float Bs[BK][BN + 4];

    int tid  = threadIdx.x;
    int arow = tid >> 1;
    int ak   = (tid & 1) * 4;
    bool avalid = (m0 + arow) < cnt;
    const float* aptr = nullptr;
    if (avalid) {
        int tok = d_perm_tok[e * NT + m0 + arow];
        aptr = x + (size_t)tok * HD + ak;
    }
    const float* bptr = W + (size_t)(n0 + arow) * HD + ak;

    int tx = tid & 15, ty = tid >> 4;
    unsigned long long acc2[8][4];
    #pragma unroll
    for (int i = 0; i < 8; i++)
        #pragma unroll
        for (int j = 0; j < 4; j++) acc2[i][j] = 0ull;

    for (int k0 = 0; k0 < HD; k0 += BK) {
        float4 av = avalid ? *(const float4*)(aptr + k0) : make_float4(0.f, 0.f, 0.f, 0.f);
        float4 bv = *(const float4*)(bptr + k0);
        As[ak + 0][arow] = av.x; As[ak + 1][arow] = av.y;
        As[ak + 2][arow] = av.z; As[ak + 3][arow] = av.w;
        Bs[ak + 0][arow] = bv.x; Bs[ak + 1][arow] = bv.y;
        Bs[ak + 2][arow] = bv.z; Bs[ak + 3][arow] = bv.w;
        __syncthreads();
        #pragma unroll
        for (int k = 0; k < BK; k++) {
            float4 a0 = *(const float4*)&As[k][ty * 8];
            float4 a1 = *(const float4*)&As[k][ty * 8 + 4];
            float4 b0 = *(const float4*)&Bs[k][tx * 8];
            float4 b1 = *(const float4*)&Bs[k][tx * 8 + 4];
            unsigned long long bp[4];
            bp[0] = pk2(b0.x, b0.y); bp[1] = pk2(b0.z, b0.w);
            bp[2] = pk2(b1.x, b1.y); bp[3] = pk2(b1.z, b1.w);
            float aa[8] = {a0.x, a0.y, a0.z, a0.w, a1.x, a1.y, a1.z, a1.w};
            #pragma unroll
            for (int i = 0; i < 8; i++) {
                unsigned long long ap = pk2(aa[i], aa[i]);
                #pragma unroll
                for (int j = 0; j < 4; j++) fma2(acc2[i][j], ap, bp[j]);
            }
        }
        __syncthreads();
    }

    #pragma unroll
    for (int i = 0; i < 8; i++) {
        int m = m0 + ty * 8 + i;
        if (m < cnt) {
            float* orow = d_gu + (size_t)(base + m) * (2 * ID) + n0 + tx * 8;
            #pragma unroll
            for (int j = 0; j < 4; j++) {
                float2 v = unpk2(acc2[i][j]);
                orow[2 * j] = v.x; orow[2 * j + 1] = v.y;
            }
        }
    }
}

// ============================================================
// 3) SwiGLU: h = silu(gu[:, :I]) * gu[:, I:]
// ============================================================
__global__ void swiglu_kernel() {
    int total = d_offsets[NE] * ID;
    int idx = blockIdx.x * blockDim.x + threadIdx.x;
    int stride = gridDim.x * blockDim.x;
    for (int i = idx; i < total; i += stride) {
        int p = i / ID, j = i - p * ID;
        float g = d_gu[(size_t)p * (2 * ID) + j];
        float u = d_gu[(size_t)p * (2 * ID) + ID + j];
        float sig = 1.f / (1.f + expf(-g));
        d_h[i] = g * sig * u;
    }
}

// GEMM2: out[tok[m]][n] += w[m] * sum_k h[base+m][k] * w2_e[n][k]  (N=HD, K=ID)
__global__ __launch_bounds__(256) void gemm2_kernel(const float* __restrict__ w2,
                                                    float* __restrict__ out) {
    int e = blockIdx.z;
    int cnt = d_counts[e];
    int m0 = blockIdx.y * BM;
    if (m0 >= cnt) return;
    int n0 = blockIdx.x * BN;
    int base = d_offsets[e];
    const float* W = w2 + (size_t)e * HD * ID;

    __shared__ __align__(16) float As[BK][BM + 4];
    __shared__ __align__(16) float Bs[BK][BN + 4];

    int tid  = threadIdx.x;
    int arow = tid >> 1;
    int ak   = (tid & 1) * 4;
    bool avalid = (m0 + arow) < cnt;
    const float* aptr = avalid ? (d_h + (size_t)(base + m0 + arow) * ID + ak) : nullptr;
    const float* bptr = W + (size_t)(n0 + arow) * ID + ak;

    int tx = tid & 15, ty = tid >> 4;
    unsigned long long acc2[8][4];
    #pragma unroll
    for (int i = 0; i < 8; i++)
        #pragma unroll
        for (int j = 0; j < 4; j++) acc2[i][j] = 0ull;

    for (int k0 = 0; k0 < ID; k0 += BK) {
        float4 av = avalid ? *(const float4*)(aptr + k0) : make_float4(0.f, 0.f, 0.f, 0.f);
        float4 bv = *(const float4*)(bptr + k0);
        As[ak + 0][arow] = av.x; As[ak + 1][arow] = av.y;
        As[ak + 2][arow] = av.z; As[ak + 3][arow] = av.w;
        Bs[ak + 0][arow] = bv.x; Bs[ak + 1][arow] = bv.y;
        Bs[ak + 2][arow] = bv.z; Bs[ak + 3][arow] = bv.w;
        __syncthreads();
        #pragma unroll
        for (int k = 0; k < BK; k++) {
            float4 a0 = *(const float4*)&As[k][ty * 8];
            float4 a1 = *(const float4*)&As[k][ty * 8 + 4];
            float4 b0 = *(const float4*)&Bs[k][tx * 8];
            float4 b1 = *(const float4*)&Bs[k][tx * 8 + 4];
            unsigned long long bp[4];
            bp[0] = pk2(b0.x, b0.y); bp[1] = pk2(b0.z, b0.w);
            bp[2] = pk2(b1.x, b1.y); bp[3] = pk2(b1.z, b1.w);
            float aa[8] = {a0.x, a0.y, a0.z, a0.w, a1.x, a1.y, a1.z, a1.w};
            #pragma unroll
            for (int i = 0; i < 8; i++) {
                unsigned long long ap = pk2(aa[i], aa[i]);
                #pragma unroll
                for (int j = 0; j < 4; j++) fma2(acc2[i][j], ap, bp[j]);
            }
        }
        __syncthreads();
    }

    #pragma unroll
    for (int i = 0; i < 8; i++) {
        int m = m0 + ty * 8 + i;
        if (m < cnt) {
            int tok = d_perm_tok[e * NT + m];
            float cw = d_perm_w[e * NT + m];
            float* orow = out + (size_t)tok * HD + n0 + tx * 8;
            #pragma unroll
            for (int j = 0; j < 4; j++) {
                float2 v = unpk2(acc2[i][j]);
                atomicAdd(&orow[2 * j],     cw * v.x);
                atomicAdd(&orow[2 * j + 1], cw * v.y);
            }
        }
    }
}

// ============================================================
extern "C" void kernel_launch(void* const* d_in, const int* in_sizes, int n_in,
                              void* d_out, int out_size) {
    const float* x    = (const float*)d_in[0];   // [T, H]
    const float* gw   = (const float*)d_in[1];   // [E, H]
    const float* bias = (const float*)d_in[2];   // [E]
    const float* w13  = (const float*)d_in[3];   // [E, 2I, H]
    const float* w2   = (const float*)d_in[4];   // [E, H, I]
    float* out = (float*)d_out;                  // [T, H]

    zero_kernel<<<4096, 256>>>(out);
    router_kernel<<<NT, 256>>>(x, gw, bias);
    offsets_kernel<<<1, 1>>>();

    dim3 g1(2 * ID / BN, NT / BM, NE);   // (16, 32, 32)
    gemm1_kernel<<<g1, 256>>>(x, w13);

    swiglu_kernel<<<4096, 256>>>();

    dim3 g2(HD / BN, NT / BM, NE);       // (16, 32, 32)
    gemm2_kernel<<<g2, 256>>>(w2, out);
}

// round 4
// speedup vs baseline: 4.2933x; 4.2933x over previous
#include <cuda_runtime.h>
#include <cuda_fp16.h>
#include <cstdint>
#include <math.h>

#define NE 32
#define TOPK 4
#define HD 2048
#define ID 1024
#define NT 4096
#define MAXP (NT*TOPK)

// ---------------- scratch (static device globals) ----------------
__device__ int      d_counts[NE];
__device__ int      d_offsets[NE+1];
__device__ int      d_perm_tok[NE*NT];
__device__ int      d_perm_slot[NE*NT];
__device__ float    d_perm_w[NE*NT];
__device__ uint32_t d_xh[NT*HD/2];                     // fp16x2, 16MB
__device__ uint32_t d_w13h[(size_t)NE*2*ID*HD/2];      // 256MB
__device__ uint32_t d_w2h[(size_t)NE*HD*ID/2];         // 128MB
__device__ uint32_t d_hh[(size_t)MAXP*ID/2];           // 32MB
__device__ float    d_partial[(size_t)NT*TOPK*HD];     // 128MB

// ---------------- helpers ----------------
__device__ __forceinline__ uint32_t smem_u32(const void* p) {
    uint32_t a;
    asm("{ .reg .u64 t; cvta.to.shared.u64 t, %1; cvt.u32.u64 %0, t; }" : "=r"(a) : "l"(p));
    return a;
}
// pack (lo, hi) floats -> f16x2 (lo in low half)
__device__ __forceinline__ uint32_t f2h2(float lo, float hi) {
    uint32_t r;
    asm("cvt.rn.f16x2.f32 %0, %1, %2;" : "=r"(r) : "f"(hi), "f"(lo));
    return r;
}
__device__ __forceinline__ void cpa16(uint32_t dst, const void* src, uint32_t sz) {
    asm volatile("cp.async.cg.shared.global [%0], [%1], 16, %2;"
                 :: "r"(dst), "l"(src), "r"(sz) : "memory");
}
__device__ __forceinline__ void cpa_commit() {
    asm volatile("cp.async.commit_group;" ::: "memory");
}
__device__ __forceinline__ void cpa_wait2() {
    asm volatile("cp.async.wait_group 2;" ::: "memory");
}
__device__ __forceinline__ void ldsm4(uint32_t (&r)[4], uint32_t a) {
    asm volatile("ldmatrix.sync.aligned.m8n8.x4.shared.b16 {%0,%1,%2,%3}, [%4];"
                 : "=r"(r[0]), "=r"(r[1]), "=r"(r[2]), "=r"(r[3]) : "r"(a));
}
__device__ __forceinline__ void mma16816(float (&d)[4], const uint32_t (&a)[4],
                                         uint32_t b0, uint32_t b1) {
    asm volatile("mma.sync.aligned.m16n8k16.row.col.f32.f16.f16.f32 "
                 "{%0,%1,%2,%3}, {%4,%5,%6,%7}, {%8,%9}, {%0,%1,%2,%3};"
                 : "+f"(d[0]), "+f"(d[1]), "+f"(d[2]), "+f"(d[3])
                 : "r"(a[0]), "r"(a[1]), "r"(a[2]), "r"(a[3]), "r"(b0), "r"(b1));
}

// ---------------- smem geometry ----------------
#define STAGES 3
#define CHB 16384                 // one tile: 128 rows x 128B (64 fp16)
#define STG_B (2*CHB)             // A + B tiles per stage
#define SM_G1 (STAGES*STG_B)              // 98304
#define SM_G2 (STAGES*STG_B + 1024)       // + cw/rid arrays

// ============================================================
__global__ void init_kernel() {
    if (threadIdx.x < NE) d_counts[threadIdx.x] = 0;
}

// fp32 -> fp16 conversion, 8 values per iter
__global__ void conv_kernel(const float4* __restrict__ src, uint4* __restrict__ dst, int n8) {
    int i = blockIdx.x * blockDim.x + threadIdx.x;
    int stride = gridDim.x * blockDim.x;
    for (; i < n8; i += stride) {
        float4 a = src[2*i], b = src[2*i+1];
        dst[i] = make_uint4(f2h2(a.x, a.y), f2h2(a.z, a.w),
                            f2h2(b.x, b.y), f2h2(b.z, b.w));
    }
}

// router: sigmoid scores, biased top-4 (bias only for selection), renorm weights
__global__ void router_kernel(const float* __restrict__ x,
                              const float* __restrict__ gw,
                              const float* __restrict__ bias) {
    int t = blockIdx.x;
    int tid = threadIdx.x;
    int e = tid >> 3;
    int l8 = tid & 7;
    const float* xr = x + (size_t)t * HD;
    const float* gr = gw + (size_t)e * HD;
    float s = 0.f;
    for (int j = l8; j < HD; j += 8) s = fmaf(xr[j], gr[j], s);
    s += __shfl_down_sync(0xffffffffu, s, 4, 8);
    s += __shfl_down_sync(0xffffffffu, s, 2, 8);
    s += __shfl_down_sync(0xffffffffu, s, 1, 8);
    __shared__ float logits[NE];
    if (l8 == 0) logits[e] = s;
    __syncthreads();
    if (tid == 0) {
        float sc[NE], bs[NE];
        #pragma unroll
        for (int i = 0; i < NE; i++) {
            float v = 1.f / (1.f + expf(-logits[i]));
            sc[i] = v;
            bs[i] = v + bias[i];
        }
        int idx[TOPK]; float w[TOPK]; float sum = 0.f;
        #pragma unroll
        for (int k = 0; k < TOPK; k++) {
            int bi = 0; float bv = -1e30f;
            #pragma unroll
            for (int i = 0; i < NE; i++)
                if (bs[i] > bv) { bv = bs[i]; bi = i; }
            bs[bi] = -1e30f;
            idx[k] = bi; w[k] = sc[bi]; sum += sc[bi];
        }
        float inv = 1.f / sum;
        #pragma unroll
        for (int k = 0; k < TOPK; k++) {
            int ex = idx[k];
            int pos = atomicAdd(&d_counts[ex], 1);
            d_perm_tok[ex * NT + pos]  = t;
            d_perm_slot[ex * NT + pos] = k;
            d_perm_w[ex * NT + pos]    = w[k] * inv;
        }
    }
}

__global__ void offsets_kernel() {
    int acc = 0;
    for (int i = 0; i < NE; i++) { d_offsets[i] = acc; acc += d_counts[i]; }
    d_offsets[NE] = acc;
}

// ============================================================
// GEMM1: gu = x_e @ w13_e^T (fp16 mma), fused SwiGLU epilogue -> d_hh (fp16)
// CTA tile M=128 x N=128 (64 gate + 64 up rows interleaved), K-chunk 64.
// ============================================================
__global__ __launch_bounds__(256) void gemm1_mma() {
    int e = blockIdx.z;
    int cnt = d_counts[e];
    int m0 = blockIdx.y * 128;
    if (m0 >= cnt) return;
    int jj = blockIdx.x;                 // h-column block of 64
    int base = d_offsets[e];

    extern __shared__ char sm[];
    uint32_t sb = smem_u32(sm);
    int tid = threadIdx.x;

    // ---- fill setup: thread -> (tile row, 64B half) ----
    int fr = tid >> 1;
    int fs = (tid & 1) * 64;
    uint32_t fkey = (uint32_t)((fr & 7) << 4);
    uint32_t fdst = (uint32_t)(fr * 128);
    bool av = (m0 + fr) < cnt;
    const char* aSrc = (const char*)d_xh;
    if (av) aSrc += ((size_t)d_perm_tok[e * NT + m0 + fr] * HD) * 2 + fs;
    int wrow = ((fr & 1) ? ID : 0) + jj * 64 + (fr >> 1);   // interleave gate/up
    const char* bSrc = (const char*)d_w13h + ((size_t)(e * 2 * ID) + wrow) * HD * 2 + fs;

    // ---- mma setup ----
    int l = tid & 31, w = tid >> 5;
    int wm = w & 1, wn = w >> 1;
    uint32_t key = (uint32_t)((l & 7) << 4);
    uint32_t c0  = (uint32_t)((l >> 4) * 16);
    uint32_t aBase = (uint32_t)((wm * 64 + (l & 15)) * 128);
    uint32_t bBase = (uint32_t)(CHB + (wn * 32 + (l & 15)) * 128);

    float d[4][4][4];
    #pragma unroll
    for (int i = 0; i < 4; i++)
        #pragma unroll
        for (int j = 0; j < 4; j++)
            #pragma unroll
            for (int q = 0; q < 4; q++) d[i][j][q] = 0.f;

    const int NC = HD / 64;   // 32

    // prologue fills
    #pragma unroll
    for (int s = 0; s < STAGES; s++) {
        if (s < NC) {
            uint32_t s0 = sb + s * STG_B;
            const char* as = aSrc + s * 128;
            const char* bs = bSrc + s * 128;
            #pragma unroll
            for (int i = 0; i < 4; i++) {
                uint32_t so = (uint32_t)(fs + i * 16) ^ fkey;
                cpa16(s0 + fdst + so, as + i * 16, av ? 16 : 0);
                cpa16(s0 + CHB + fdst + so, bs + i * 16, 16);
            }
        }
        cpa_commit();
    }

    for (int c = 0; c < NC; c++) {
        cpa_wait2();
        __syncthreads();
        uint32_t s0 = sb + (c % STAGES) * STG_B;
        #pragma unroll
        for (int ks = 0; ks < 4; ks++) {
            uint32_t kb = (uint32_t)(ks * 32);
            uint32_t a[4][4], bfr[2][4];
            #pragma unroll
            for (int mb = 0; mb < 4; mb++)
                ldsm4(a[mb], s0 + aBase + mb * 2048 + ((kb + c0) ^ key));
            #pragma unroll
            for (int nb2 = 0; nb2 < 2; nb2++)
                ldsm4(bfr[nb2], s0 + bBase + nb2 * 2048 + ((kb + c0) ^ key));
            #pragma unroll
            for (int mb = 0; mb < 4; mb++)
                #pragma unroll
                for (int n = 0; n < 4; n++)
                    mma16816(d[mb][n], a[mb], bfr[n >> 1][n & 1], bfr[n >> 1][(n & 1) + 2]);
        }
        __syncthreads();
        int nc = c + STAGES;
        if (nc < NC) {
            uint32_t sf = sb + (c % STAGES) * STG_B;
            const char* as = aSrc + nc * 128;
            const char* bs = bSrc + nc * 128;
            #pragma unroll
            for (int i = 0; i < 4; i++) {
                uint32_t so = (uint32_t)(fs + i * 16) ^ fkey;
                cpa16(sf + fdst + so, as + i * 16, av ? 16 : 0);
                cpa16(sf + CHB + fdst + so, bs + i * 16, 16);
            }
        }
        cpa_commit();
    }

    // ---- epilogue: SwiGLU (cols alternate gate,up) -> smem stage0 -> d_hh ----
    __half* smh = (__half*)sm;     // 128 x 64 fp16 = 16KB (stage0 reuse, all mma done)
    int rbase = wm * 64 + (l >> 2);
    int tcol  = wn * 16 + (l & 3);
    #pragma unroll
    for (int mb = 0; mb < 4; mb++) {
        int r0 = rbase + mb * 16;
        #pragma unroll
        for (int nb = 0; nb < 4; nb++) {
            int tc = tcol + nb * 4;
            float g0 = d[mb][nb][0], u0 = d[mb][nb][1];
            float g1 = d[mb][nb][2], u1 = d[mb][nb][3];
            float h0 = g0 / (1.f + __expf(-g0)) * u0;
            float h1 = g1 / (1.f + __expf(-g1)) * u1;
            smh[r0 * 64 + tc]       = __float2half(h0);
            smh[(r0 + 8) * 64 + tc] = __float2half(h1);
        }
    }
    __syncthreads();
    int rr = tid >> 1;
    int hh = (tid & 1) * 32;
    if ((m0 + rr) < cnt) {
        const uint4* s4 = (const uint4*)((const char*)sm + (rr * 64 + hh) * 2);
        uint4* g4 = (uint4*)((char*)d_hh + (((size_t)(base + m0 + rr)) * ID + jj * 64 + hh) * 2);
        g4[0] = s4[0]; g4[1] = s4[1]; g4[2] = s4[2]; g4[3] = s4[3];
    }
}

// ============================================================
// GEMM2: y = h_e @ w2_e^T (fp16 mma), epilogue writes cw*y -> d_partial[tok*4+slot]
// ============================================================
__global__ __launch_bounds__(256) void gemm2_mma() {
    int e = blockIdx.z;
    int cnt = d_counts[e];
    int m0 = blockIdx.y * 128;
    if (m0 >= cnt) return;
    int n0 = blockIdx.x * 128;
    int base = d_offsets[e];

    extern __shared__ char sm[];
    uint32_t sb = smem_u32(sm);
    int tid = threadIdx.x;

    float* s_cw = (float*)(sm + STAGES * STG_B);
    int*   s_ri = (int*)(sm + STAGES * STG_B + 512);
    if (tid < 128) {
        int m = m0 + tid;
        if (m < cnt) {
            s_cw[tid] = d_perm_w[e * NT + m];
            s_ri[tid] = d_perm_tok[e * NT + m] * TOPK + d_perm_slot[e * NT + m];
        }
    }

    int fr = tid >> 1;
    int fs = (tid & 1) * 64;
    uint32_t fkey = (uint32_t)((fr & 7) << 4);
    uint32_t fdst = (uint32_t)(fr * 128);
    bool av = (m0 + fr) < cnt;
    const char* aSrc = (const char*)d_hh;
    if (av) aSrc += ((size_t)(base + m0 + fr) * ID) * 2 + fs;
    const char* bSrc = (const char*)d_w2h + ((size_t)(e * HD) + n0 + fr) * ID * 2 + fs;

    int l = tid & 31, w = tid >> 5;
    int wm = w & 1, wn = w >> 1;
    uint32_t key = (uint32_t)((l & 7) << 4);
    uint32_t c0  = (uint32_t)((l >> 4) * 16);
    uint32_t aBase = (uint32_t)((wm * 64 + (l & 15)) * 128);
    uint32_t bBase = (uint32_t)(CHB + (wn * 32 + (l & 15)) * 128);

    float d[4][4][4];
    #pragma unroll
    for (int i = 0; i < 4; i++)
        #pragma unroll
        for (int j = 0; j < 4; j++)
            #pragma unroll
            for (int q = 0; q < 4; q++) d[i][j][q] = 0.f;

    const int NC = ID / 64;   // 16

    #pragma unroll
    for (int s = 0; s < STAGES; s++) {
        if (s < NC) {
            uint32_t s0 = sb + s * STG_B;
            const char* as = aSrc + s * 128;
            const char* bs = bSrc + s * 128;
            #pragma unroll
            for (int i = 0; i < 4; i++) {
                uint32_t so = (uint32_t)(fs + i * 16) ^ fkey;
                cpa16(s0 + fdst + so, as + i * 16, av ? 16 : 0);
                cpa16(s0 + CHB + fdst + so, bs + i * 16, 16);
            }
        }
        cpa_commit();
    }

    for (int c = 0; c < NC; c++) {
        cpa_wait2();
        __syncthreads();
        uint32_t s0 = sb + (c % STAGES) * STG_B;
        #pragma unroll
        for (int ks = 0; ks < 4; ks++) {
            uint32_t kb = (uint32_t)(ks * 32);
            uint32_t a[4][4], bfr[2][4];
            #pragma unroll
            for (int mb = 0; mb < 4; mb++)
                ldsm4(a[mb], s0 + aBase + mb * 2048 + ((kb + c0) ^ key));
            #pragma unroll
            for (int nb2 = 0; nb2 < 2; nb2++)
                ldsm4(bfr[nb2], s0 + bBase + nb2 * 2048 + ((kb + c0) ^ key));
            #pragma unroll
            for (int mb = 0; mb < 4; mb++)
                #pragma unroll
                for (int n = 0; n < 4; n++)
                    mma16816(d[mb][n], a[mb], bfr[n >> 1][n & 1], bfr[n >> 1][(n & 1) + 2]);
        }
        __syncthreads();
        int nc = c + STAGES;
        if (nc < NC) {
            uint32_t sf = sb + (c % STAGES) * STG_B;
            const char* as = aSrc + nc * 128;
            const char* bs = bSrc + nc * 128;
            #pragma unroll
            for (int i = 0; i < 4; i++) {
                uint32_t so = (uint32_t)(fs + i * 16) ^ fkey;
                cpa16(sf + fdst + so, as + i * 16, av ? 16 : 0);
                cpa16(sf + CHB + fdst + so, bs + i * 16, 16);
            }
        }
        cpa_commit();
    }

    // ---- epilogue: scale by cw, store to d_partial ----
    int rbase = wm * 64 + (l >> 2);
    int cb = n0 + wn * 32 + 2 * (l & 3);
    #pragma unroll
    for (int mb = 0; mb < 4; mb++) {
        int r0 = rbase + mb * 16;
        int r1 = r0 + 8;
        bool v0 = (m0 + r0) < cnt;
        bool v1 = (m0 + r1) < cnt;
        float cw0 = v0 ? s_cw[r0] : 0.f;
        float cw1 = v1 ? s_cw[r1] : 0.f;
        size_t p0 = v0 ? (size_t)s_ri[r0] * HD : 0;
        size_t p1 = v1 ? (size_t)s_ri[r1] * HD : 0;
        #pragma unroll
        for (int nb = 0; nb < 4; nb++) {
            int col = cb + nb * 8;
            if (v0) {
                float2 o = make_float2(cw0 * d[mb][nb][0], cw0 * d[mb][nb][1]);
                *(float2*)(d_partial + p0 + col) = o;
            }
            if (v1) {
                float2 o = make_float2(cw1 * d[mb][nb][2], cw1 * d[mb][nb][3]);
                *(float2*)(d_partial + p1 + col) = o;
            }
        }
    }
}

// ============================================================
__global__ void combine_kernel(float* __restrict__ out) {
    int i = blockIdx.x * blockDim.x + threadIdx.x;
    int stride = gridDim.x * blockDim.x;
    const int n = NT * HD / 4;
    const float4* p = (const float4*)d_partial;
    float4* o = (float4*)out;
    for (; i < n; i += stride) {
        int t = i >> 9;                 // HD/4 = 512
        int col = i & 511;
        size_t b = ((size_t)t * TOPK) * 512 + col;
        float4 a0 = p[b], a1 = p[b + 512], a2 = p[b + 1024], a3 = p[b + 1536];
        float4 r;
        r.x = a0.x + a1.x + a2.x + a3.x;
        r.y = a0.y + a1.y + a2.y + a3.y;
        r.z = a0.z + a1.z + a2.z + a3.z;
        r.w = a0.w + a1.w + a2.w + a3.w;
        o[i] = r;
    }
}

// ============================================================
extern "C" void kernel_launch(void* const* d_in, const int* in_sizes, int n_in,
                              void* d_out, int out_size) {
    const float* x    = (const float*)d_in[0];   // [T, H]
    const float* gw   = (const float*)d_in[1];   // [E, H]
    const float* bias = (const float*)d_in[2];   // [E]
    const float* w13  = (const float*)d_in[3];   // [E, 2I, H]
    const float* w2   = (const float*)d_in[4];   // [E, H, I]
    float* out = (float*)d_out;                  // [T, H]

    static int inited = 0;
    if (!inited) {
        cudaFuncSetAttribute(gemm1_mma, cudaFuncAttributeMaxDynamicSharedMemorySize, SM_G1);
        cudaFuncSetAttribute(gemm2_mma, cudaFuncAttributeMaxDynamicSharedMemorySize, SM_G2);
        inited = 1;
    }

    init_kernel<<<1, 32>>>();

    uint4* w13h_p; cudaGetSymbolAddress((void**)&w13h_p, d_w13h);
    uint4* w2h_p;  cudaGetSymbolAddress((void**)&w2h_p,  d_w2h);
    uint4* xh_p;   cudaGetSymbolAddress((void**)&xh_p,   d_xh);

    conv_kernel<<<8192, 256>>>((const float4*)w13, (uint4*)w13h_p, NE * 2 * ID * (HD / 8));
    conv_kernel<<<4096, 256>>>((const float4*)w2,  (uint4*)w2h_p,  NE * HD * (ID / 8));
    conv_kernel<<<1024, 256>>>((const float4*)x,   (uint4*)xh_p,   NT * (HD / 8));

    router_kernel<<<NT, 256>>>(x, gw, bias);
    offsets_kernel<<<1, 1>>>();

    dim3 g1(ID / 64, NT / 128, NE);      // (16, 32, 32)
    gemm1_mma<<<g1, 256, SM_G1>>>();

    dim3 g2(HD / 128, NT / 128, NE);     // (16, 32, 32)
    gemm2_mma<<<g2, 256, SM_G2>>>();

    combine_kernel<<<2048, 256>>>(out);
}